// round 15
// baseline (speedup 1.0000x reference)
#include <cuda_runtime.h>
#include <cuda_fp16.h>
#include <math.h>
#include <stdint.h>

// ---------------- problem constants (fixed by dataset) ----------------
#define NODES 50000
#define NEDGE 600000
#define ETOT  (NEDGE + NODES)   // edges + self loops
#define FIN   256
#define HID   128
#define NCLS  20
#define NEG_SLOPE 0.2f

#define SCAN_BLK 1024
#define NTILES ((NODES + SCAN_BLK - 1) / SCAN_BLK)   // 49

// weight-transpose (half) offsets in g_wt
#define WT1_OFF 0
#define WT2_OFF (FIN * HID)
#define WTM_OFF (FIN * HID + HID * HID)
#define WT_TOTAL (FIN * HID + 2 * HID * HID)

// ---------------- scratch (static device globals) ----------------
__device__ __align__(16) float  g_h  [(size_t)NODES * HID];  // f32 GEMM out (MLP head)
__device__ __align__(16) __half g_h16[(size_t)NODES * HID];  // fp16 GEMM out (GAT layers)
__device__ __align__(16) __half g_xh [(size_t)NODES * FIN];  // half copy of input x
__device__ __align__(16) __half g_x2h[(size_t)NODES * HID];  // half aggregation outputs
__device__ __align__(16) float  g_as [NODES];
__device__ __align__(16) float  g_ad [NODES];
__device__ __align__(16) __half g_wt [WT_TOTAL];             // transposed half weights
__device__ int g_cnt[NODES];
__device__ int g_rowptr[NODES + 1];
__device__ int g_fill[NODES];
__device__ int g_col[ETOT];
__device__ int g_tilesum[NTILES];
__device__ int g_tileoff[NTILES];
__device__ unsigned g_asmax[2];

// ---------------- streams/events for forked graph capture ----------------
struct GraphStreams {
    cudaStream_t side = nullptr;
    cudaEvent_t ev_fork = nullptr, ev_join = nullptr;
    GraphStreams() {
        cudaStreamCreateWithFlags(&side, cudaStreamNonBlocking);
        cudaEventCreateWithFlags(&ev_fork, cudaEventDisableTiming);
        cudaEventCreateWithFlags(&ev_join, cudaEventDisableTiming);
    }
};
static GraphStreams g_gs;

// ---------------- order-preserving float<->uint encoding ----------------
__device__ __forceinline__ unsigned enc_ord(float f) {
    unsigned u = __float_as_uint(f);
    return (u & 0x80000000u) ? ~u : (u | 0x80000000u);
}
__device__ __forceinline__ float dec_ord(unsigned k) {
    return (k & 0x80000000u) ? __uint_as_float(k & 0x7fffffffu)
                             : __uint_as_float(~k);
}

// ---------------- cp.async helpers ----------------
__device__ __forceinline__ void cp_async16(uint32_t dst, const void* src, int src_bytes) {
    asm volatile("cp.async.cg.shared.global [%0], [%1], 16, %2;"
                 :: "r"(dst), "l"(src), "r"(src_bytes));
}
__device__ __forceinline__ void cp_commit() { asm volatile("cp.async.commit_group;"); }
template <int N>
__device__ __forceinline__ void cp_wait() { asm volatile("cp.async.wait_group %0;" :: "n"(N)); }

__device__ __forceinline__ void mma_f16(float* d, const uint32_t* a, const uint32_t* b) {
    asm volatile(
        "mma.sync.aligned.m16n8k16.row.col.f32.f16.f16.f32 "
        "{%0,%1,%2,%3}, {%4,%5,%6,%7}, {%8,%9}, {%0,%1,%2,%3};"
        : "+f"(d[0]), "+f"(d[1]), "+f"(d[2]), "+f"(d[3])
        : "r"(a[0]), "r"(a[1]), "r"(a[2]), "r"(a[3]), "r"(b[0]), "r"(b[1]));
}

// per-block dtype probe
__device__ __forceinline__ int probe_is64_block(const void* ei) {
    __shared__ int s_is64;
    if (threadIdx.x == 0) {
        const unsigned* p = (const unsigned*)ei;
        s_is64 = ((p[1] | p[3] | p[5] | p[7]) == 0u) ? 1 : 0;
    }
    __syncthreads();
    return s_is64;
}

__device__ __forceinline__ int load_edge_i(const void* ei, long long idx, int is64) {
    int v;
    if (is64) v = (int)((const long long*)ei)[idx];
    else      v = ((const int*)ei)[idx];
    return (v < 0) ? 0 : (v >= NODES ? NODES - 1 : v);
}

// ---------------- converts ----------------
// WT[n*K+k] = half(W[k*N+n])
__global__ void convert_w_k(const float* __restrict__ W, int K, int wt_off) {
    int idx = blockIdx.x * blockDim.x + threadIdx.x;
    if (idx >= K * HID) return;
    int n = idx % HID, k = idx / HID;
    g_wt[wt_off + n * K + k] = __float2half(W[idx]);
}

// xh = half(x), vectorized: 4 floats -> 4 halves per thread
__global__ void convert_x_k(const float* __restrict__ x) {
    int i = blockIdx.x * blockDim.x + threadIdx.x;
    const int total4 = NODES * FIN / 4;
    if (i >= total4) return;
    float4 v = reinterpret_cast<const float4*>(x)[i];
    __half2 h0 = __floats2half2_rn(v.x, v.y);
    __half2 h1 = __floats2half2_rn(v.z, v.w);
    uint2 packed = make_uint2(*reinterpret_cast<uint32_t*>(&h0),
                              *reinterpret_cast<uint32_t*>(&h1));
    reinterpret_cast<uint2*>(g_xh)[i] = packed;
}

// ---------------- CSR build ----------------
__global__ void count_edges_k(const void* __restrict__ ei) {
    int is64 = probe_is64_block(ei);
    int e = blockIdx.x * blockDim.x + threadIdx.x;
    if (e >= ETOT) return;
    int dst = (e < NEDGE) ? load_edge_i(ei, (long long)NEDGE + e, is64) : (e - NEDGE);
    atomicAdd(&g_cnt[dst], 1);
}

__global__ void scan_phase1_k() {
    __shared__ int sh[SCAN_BLK];
    int t = threadIdx.x;
    int i = blockIdx.x * SCAN_BLK + t;
    int v = (i < NODES) ? g_cnt[i] : 0;
    sh[t] = v;
    __syncthreads();
    for (int off = 1; off < SCAN_BLK; off <<= 1) {
        int x = 0;
        if (t >= off) x = sh[t - off];
        __syncthreads();
        sh[t] += x;
        __syncthreads();
    }
    if (i < NODES) {
        int loc = sh[t] - v;
        g_rowptr[i] = loc;
        g_fill[i]   = loc;
        g_cnt[i]    = 0;
    }
    if (t == SCAN_BLK - 1) g_tilesum[blockIdx.x] = sh[t];
}

__global__ void scan_phase2_k() {
    __shared__ int sh[64];
    int t = threadIdx.x;
    int v = (t < NTILES) ? g_tilesum[t] : 0;
    sh[t] = v;
    __syncthreads();
    for (int off = 1; off < 64; off <<= 1) {
        int x = 0;
        if (t >= off) x = sh[t - off];
        __syncthreads();
        sh[t] += x;
        __syncthreads();
    }
    if (t < NTILES) g_tileoff[t] = sh[t] - v;
    if (t == 63) g_rowptr[NODES] = sh[63];
}

__global__ void fill_edges_k(const void* __restrict__ ei) {
    int is64 = probe_is64_block(ei);
    int e = blockIdx.x * blockDim.x + threadIdx.x;
    if (e >= ETOT) return;
    int src, dst;
    if (e < NEDGE) {
        src = load_edge_i(ei, e, is64);
        dst = load_edge_i(ei, (long long)NEDGE + e, is64);
    } else {
        src = dst = e - NEDGE;
    }
    int p = atomicAdd(&g_fill[dst], 1) + g_tileoff[dst >> 10];
    g_col[p] = src;
}

// ---------------- FP16 tensor-core GEMM, all-half operands ----------------
// A: half (g_xh if ASEL==0 else g_x2h). B: half g_wt+wt_off, [n][k].
#define ASTRH 24    // halves; (12*gid+tig) mod 32 distinct -> conflict-free
#define BSTRT 24

template <int ASEL, bool BIAS, bool RELU, bool DOTS, bool H16>
__global__ __launch_bounds__(256, 2)
void gemm_f16_k(int wt_off,
                const float* __restrict__ bias,
                const float* __restrict__ a_src, const float* __restrict__ a_dst,
                int M, int K, int layer) {
    const int BM = 128, BN = 128, BK = 16;
    const __half* A = (ASEL == 0) ? (const __half*)g_xh : (const __half*)g_x2h;
    const __half* Bw = g_wt + wt_off;

    __shared__ __half As [2][BM][ASTRH];   // [m][k] within tile
    __shared__ __half BsT[2][BN][BSTRT];   // [n][k] within tile
    __shared__ float sh_s[BM];
    __shared__ float sh_d[BM];

    const int tid  = threadIdx.x;
    const int lane = tid & 31;
    const int wid  = tid >> 5;
    const int wm   = (wid >> 2) * 64;
    const int wn   = (wid & 3) * 32;
    const int gid  = lane >> 2;
    const int tig  = lane & 3;
    const int block_row = blockIdx.x * BM;

    const int t_row = tid >> 1;      // 0..127
    const int t_c   = tid & 1;       // 16B chunk index within 32B row

    if (DOTS && tid < BM) { sh_s[tid] = 0.f; sh_d[tid] = 0.f; }

    float acc[4][4][4];
    #pragma unroll
    for (int mt = 0; mt < 4; mt++)
        #pragma unroll
        for (int nt = 0; nt < 4; nt++)
            #pragma unroll
            for (int r = 0; r < 4; r++) acc[mt][nt][r] = 0.f;

    auto load_tile = [&](int k0, int s) {
        // A: 128 rows x 16 halves (32B) per tile
        {
            int grow = block_row + t_row;
            const __half* src = A + (size_t)grow * K + k0 + t_c * 8;
            uint32_t dst = (uint32_t)__cvta_generic_to_shared(&As[s][t_row][t_c * 8]);
            cp_async16(dst, src, (grow < M) ? 16 : 0);
        }
        // B: 128 rows x 16 halves
        {
            const __half* src = Bw + (size_t)t_row * K + k0 + t_c * 8;
            uint32_t dst = (uint32_t)__cvta_generic_to_shared(&BsT[s][t_row][t_c * 8]);
            cp_async16(dst, src, 16);
        }
    };

    load_tile(0, 0);
    cp_commit();

    int buf = 0;
    for (int k0 = 0; k0 < K; k0 += BK) {
        if (k0 + BK < K) load_tile(k0 + BK, buf ^ 1);
        cp_commit();
        cp_wait<1>();
        __syncthreads();

        uint32_t afr[4][4];
        #pragma unroll
        for (int mt = 0; mt < 4; mt++) {
            int r = wm + mt * 16;
            afr[mt][0] = *reinterpret_cast<const uint32_t*>(&As[buf][r + gid    ][2 * tig    ]);
            afr[mt][1] = *reinterpret_cast<const uint32_t*>(&As[buf][r + gid + 8][2 * tig    ]);
            afr[mt][2] = *reinterpret_cast<const uint32_t*>(&As[buf][r + gid    ][2 * tig + 8]);
            afr[mt][3] = *reinterpret_cast<const uint32_t*>(&As[buf][r + gid + 8][2 * tig + 8]);
        }
        uint32_t bfr[4][2];
        #pragma unroll
        for (int nt = 0; nt < 4; nt++) {
            int c = wn + nt * 8 + gid;
            bfr[nt][0] = *reinterpret_cast<const uint32_t*>(&BsT[buf][c][2 * tig    ]);
            bfr[nt][1] = *reinterpret_cast<const uint32_t*>(&BsT[buf][c][2 * tig + 8]);
        }
        #pragma unroll
        for (int mt = 0; mt < 4; mt++)
            #pragma unroll
            for (int nt = 0; nt < 4; nt++)
                mma_f16(acc[mt][nt], afr[mt], bfr[nt]);

        __syncthreads();
        buf ^= 1;
    }
    cp_wait<0>();

    float vs[4][2], vd[4][2];
    if (DOTS) {
        #pragma unroll
        for (int nt = 0; nt < 4; nt++) {
            int col = wn + nt * 8 + 2 * tig;
            vs[nt][0] = a_src[col];     vs[nt][1] = a_src[col + 1];
            vd[nt][0] = a_dst[col];     vd[nt][1] = a_dst[col + 1];
        }
    }

    #pragma unroll
    for (int mt = 0; mt < 4; mt++) {
        #pragma unroll
        for (int half = 0; half < 2; half++) {
            int rloc = wm + mt * 16 + gid + half * 8;
            int grow = block_row + rloc;
            if (grow >= M) continue;
            float ps = 0.f, pd = 0.f;
            #pragma unroll
            for (int nt = 0; nt < 4; nt++) {
                int col = wn + nt * 8 + 2 * tig;
                float v0 = acc[mt][nt][2 * half + 0];
                float v1 = acc[mt][nt][2 * half + 1];
                if (BIAS) { v0 += bias[col]; v1 += bias[col + 1]; }
                if (RELU) { v0 = fmaxf(v0, 0.f); v1 = fmaxf(v1, 0.f); }
                if (DOTS) {
                    ps = fmaf(v0, vs[nt][0], fmaf(v1, vs[nt][1], ps));
                    pd = fmaf(v0, vd[nt][0], fmaf(v1, vd[nt][1], pd));
                }
                if (H16) {
                    __half2 hv = __floats2half2_rn(v0, v1);
                    *reinterpret_cast<__half2*>(g_h16 + (size_t)grow * HID + col) = hv;
                } else {
                    float2* dst = reinterpret_cast<float2*>(g_h + (size_t)grow * HID + col);
                    *dst = make_float2(v0, v1);
                }
            }
            if (DOTS) {
                atomicAdd(&sh_s[rloc], ps);
                atomicAdd(&sh_d[rloc], pd);
            }
        }
    }

    if (DOTS) {
        __syncthreads();
        if (tid < BM) {
            int grow = block_row + tid;
            float sv = -INFINITY;
            if (grow < M) {
                sv = sh_s[tid];
                g_as[grow] = sv;
                g_ad[grow] = sh_d[tid];
            }
            #pragma unroll
            for (int o = 16; o; o >>= 1)
                sv = fmaxf(sv, __shfl_xor_sync(0xffffffffu, sv, o));
            if ((tid & 31) == 0)
                atomicMax(&g_asmax[layer], enc_ord(sv));
        }
    }
}

// ---------------- GAT aggregation: warp/node, single pass, half output ----------
template <bool RELU>
__global__ void gat_aggregate_k(const float* __restrict__ bias, int layer) {
    int node = blockIdx.x * (blockDim.x >> 5) + (threadIdx.x >> 5);
    if (node >= NODES) return;
    int lane = threadIdx.x & 31;
    int beg = g_rowptr[node] + g_tileoff[node >> 10];
    int end;
    if (node + 1 < NODES) end = g_rowptr[node + 1] + g_tileoff[(node + 1) >> 10];
    else                  end = g_rowptr[NODES];
    float adn = g_ad[node];

    float m = dec_ord(g_asmax[layer]) + adn;
    m = m > 0.f ? m : NEG_SLOPE * m;

    float4 acc = make_float4(0.f, 0.f, 0.f, 0.f);
    float denom = 0.f;
    #pragma unroll 2
    for (int e = beg; e < end; e++) {
        int s = g_col[e];
        float l = g_as[s] + adn;
        l = l > 0.f ? l : NEG_SLOPE * l;
        float w = __expf(l - m);
        denom += w;
        uint2 raw = reinterpret_cast<const uint2*>(g_h16 + (size_t)s * HID)[lane];
        __half2 p0 = *reinterpret_cast<__half2*>(&raw.x);
        __half2 p1 = *reinterpret_cast<__half2*>(&raw.y);
        float2 f0 = __half22float2(p0);
        float2 f1 = __half22float2(p1);
        acc.x = fmaf(w, f0.x, acc.x);
        acc.y = fmaf(w, f0.y, acc.y);
        acc.z = fmaf(w, f1.x, acc.z);
        acc.w = fmaf(w, f1.y, acc.w);
    }
    float inv = 1.f / denom;
    float4 b4 = reinterpret_cast<const float4*>(bias)[lane];
    float o0 = acc.x * inv + b4.x;
    float o1 = acc.y * inv + b4.y;
    float o2 = acc.z * inv + b4.z;
    float o3 = acc.w * inv + b4.w;
    if (RELU) {
        o0 = fmaxf(o0, 0.f); o1 = fmaxf(o1, 0.f);
        o2 = fmaxf(o2, 0.f); o3 = fmaxf(o3, 0.f);
    }
    __half2 h0 = __floats2half2_rn(o0, o1);
    __half2 h1 = __floats2half2_rn(o2, o3);
    uint2 packed = make_uint2(*reinterpret_cast<uint32_t*>(&h0),
                              *reinterpret_cast<uint32_t*>(&h1));
    reinterpret_cast<uint2*>(g_x2h + (size_t)node * HID)[lane] = packed;
}

// ---------------- final: out = sigmoid(g_h @ Wm2 + bm2), vectorized ----------------
#define MLP_ROWS 64
__global__ __launch_bounds__(256)
void mlp_out_k(const float* __restrict__ W, const float* __restrict__ b,
               float* __restrict__ out) {
    __shared__ float Wst[NCLS][HID + 4];
    __shared__ float bs[NCLS];
    __shared__ __align__(16) float hs[MLP_ROWS][HID];

    int tid = threadIdx.x;
    for (int i = tid; i < HID * NCLS; i += blockDim.x)
        Wst[i % NCLS][i / NCLS] = W[i];
    if (tid < NCLS) bs[tid] = b[tid];

    int row0 = blockIdx.x * MLP_ROWS;
    const float4* src = reinterpret_cast<const float4*>(g_h + (size_t)row0 * HID);
    float4* dst4 = reinterpret_cast<float4*>(&hs[0][0]);
    int n4 = min(MLP_ROWS, NODES - row0) * (HID / 4);
    for (int i = tid; i < n4; i += blockDim.x) dst4[i] = src[i];
    __syncthreads();

    int nout = min(MLP_ROWS, NODES - row0) * NCLS;
    for (int o = tid; o < nout; o += blockDim.x) {
        int rl = o / NCLS, c = o % NCLS;
        const float4* zr = reinterpret_cast<const float4*>(&hs[rl][0]);
        const float4* wc = reinterpret_cast<const float4*>(&Wst[c][0]);
        float acc = bs[c];
        #pragma unroll
        for (int k = 0; k < HID / 4; k++) {
            float4 z = zr[k];
            float4 w = wc[k];
            acc = fmaf(z.x, w.x, acc);
            acc = fmaf(z.y, w.y, acc);
            acc = fmaf(z.z, w.z, acc);
            acc = fmaf(z.w, w.w, acc);
        }
        out[(size_t)(row0 + rl) * NCLS + c] = 1.f / (1.f + __expf(-acc));
    }
}

// ---------------- launch ----------------
extern "C" void kernel_launch(void* const* d_in, const int* in_sizes, int n_in,
                              void* d_out, int out_size) {
    const float* x    = (const float*)d_in[0];
    const void*  ei   = d_in[1];
    const float* W1   = (const float*)d_in[2];
    const float* as1  = (const float*)d_in[3];
    const float* ad1  = (const float*)d_in[4];
    const float* b1   = (const float*)d_in[5];
    const float* W2   = (const float*)d_in[6];
    const float* as2  = (const float*)d_in[7];
    const float* ad2  = (const float*)d_in[8];
    const float* b2   = (const float*)d_in[9];
    const float* Wm1  = (const float*)d_in[10];
    const float* bm1  = (const float*)d_in[11];
    const float* Wm2  = (const float*)d_in[12];
    const float* bm2  = (const float*)d_in[13];
    float*       out  = (float*)d_out;

    const int gemm_grid  = (NODES + 127) / 128;
    const int warps_grid = (NODES + 7) / 8;
    const int edge_grid  = (ETOT + 255) / 256;

    // --- fork: CSR build on side stream; converts + GEMM1 on main ---
    cudaEventRecord(g_gs.ev_fork, 0);
    cudaStreamWaitEvent(g_gs.side, g_gs.ev_fork, 0);

    count_edges_k<<<edge_grid, 256, 0, g_gs.side>>>(ei);
    scan_phase1_k<<<NTILES, SCAN_BLK, 0, g_gs.side>>>();
    scan_phase2_k<<<1, 64, 0, g_gs.side>>>();
    fill_edges_k<<<edge_grid, 256, 0, g_gs.side>>>(ei);
    cudaEventRecord(g_gs.ev_join, g_gs.side);

    // main: convert weights and x to half (all hidden under CSR chain)
    convert_w_k<<<(FIN * HID + 255) / 256, 256>>>(W1,  FIN, WT1_OFF);
    convert_w_k<<<(HID * HID + 255) / 256, 256>>>(W2,  HID, WT2_OFF);
    convert_w_k<<<(HID * HID + 255) / 256, 256>>>(Wm1, HID, WTM_OFF);
    convert_x_k<<<(NODES * FIN / 4 + 255) / 256, 256>>>(x);

    // GAT layer 1 GEMM (+ fused dots/asmax, fp16 h)
    gemm_f16_k<0, false, false, true, true><<<gemm_grid, 256>>>(WT1_OFF, nullptr, as1, ad1, NODES, FIN, 0);

    cudaStreamWaitEvent(0, g_gs.ev_join, 0);
    gat_aggregate_k<true><<<warps_grid, 256>>>(b1, 0);

    // --- GAT layer 2 ---
    gemm_f16_k<1, false, false, true, true><<<gemm_grid, 256>>>(WT2_OFF, nullptr, as2, ad2, NODES, HID, 1);
    gat_aggregate_k<false><<<warps_grid, 256>>>(b2, 1);

    // --- MLP head (f32 out) ---
    gemm_f16_k<1, true, true, false, false><<<gemm_grid, 256>>>(WTM_OFF, bm1, nullptr, nullptr, NODES, HID, 0);
    mlp_out_k<<<(NODES + MLP_ROWS - 1) / MLP_ROWS, 256>>>(Wm2, bm2, out);
}

// round 16
// speedup vs baseline: 1.0747x; 1.0747x over previous
#include <cuda_runtime.h>
#include <cuda_fp16.h>
#include <math.h>
#include <stdint.h>

// ---------------- problem constants (fixed by dataset) ----------------
#define NODES 50000
#define NEDGE 600000
#define ETOT  (NEDGE + NODES)   // edges + self loops
#define FIN   256
#define HID   128
#define NCLS  20
#define NEG_SLOPE 0.2f

#define SCAN_BLK 1024
#define NTILES ((NODES + SCAN_BLK - 1) / SCAN_BLK)   // 49

// ---------------- scratch (static device globals) ----------------
__device__ __align__(16) float  g_h  [(size_t)NODES * HID];  // f32 GEMM out (MLP head)
__device__ __align__(16) __half g_h16[(size_t)NODES * HID];  // fp16 GEMM out (GAT layers)
__device__ __align__(16) float  g_x2 [(size_t)NODES * HID];  // aggregation outputs
__device__ __align__(16) float  g_as [NODES];
__device__ __align__(16) float  g_ad [NODES];
__device__ int g_cnt[NODES];
__device__ int g_rowptr[NODES + 1];   // LOCAL exclusive scan per 1024-tile; [NODES]=total
__device__ int g_fill[NODES];
__device__ int g_col[ETOT];
__device__ int g_tilesum[NTILES];
__device__ int g_tileoff[NTILES];
__device__ unsigned g_asmax[2];

// ---------------- streams/events for forked graph capture ----------------
struct GraphStreams {
    cudaStream_t side = nullptr;
    cudaEvent_t ev_fork = nullptr, ev_join = nullptr;
    GraphStreams() {
        cudaStreamCreateWithFlags(&side, cudaStreamNonBlocking);
        cudaEventCreateWithFlags(&ev_fork, cudaEventDisableTiming);
        cudaEventCreateWithFlags(&ev_join, cudaEventDisableTiming);
    }
};
static GraphStreams g_gs;

// ---------------- order-preserving float<->uint encoding ----------------
__device__ __forceinline__ unsigned enc_ord(float f) {
    unsigned u = __float_as_uint(f);
    return (u & 0x80000000u) ? ~u : (u | 0x80000000u);
}
__device__ __forceinline__ float dec_ord(unsigned k) {
    return (k & 0x80000000u) ? __uint_as_float(k & 0x7fffffffu)
                             : __uint_as_float(~k);
}

// ---------------- cp.async helpers ----------------
__device__ __forceinline__ void cp_async16(uint32_t dst, const void* src, int src_bytes) {
    asm volatile("cp.async.cg.shared.global [%0], [%1], 16, %2;"
                 :: "r"(dst), "l"(src), "r"(src_bytes));
}
__device__ __forceinline__ void cp_commit() { asm volatile("cp.async.commit_group;"); }
template <int N>
__device__ __forceinline__ void cp_wait() { asm volatile("cp.async.wait_group %0;" :: "n"(N)); }

__device__ __forceinline__ uint32_t f2tf32(float x) {
    uint32_t r;
    asm("cvt.rna.tf32.f32 %0, %1;" : "=r"(r) : "f"(x));
    return r;
}
__device__ __forceinline__ void mma_tf32(float* d, const uint32_t* a, const uint32_t* b) {
    asm volatile(
        "mma.sync.aligned.m16n8k8.row.col.f32.tf32.tf32.f32 "
        "{%0,%1,%2,%3}, {%4,%5,%6,%7}, {%8,%9}, {%0,%1,%2,%3};"
        : "+f"(d[0]), "+f"(d[1]), "+f"(d[2]), "+f"(d[3])
        : "r"(a[0]), "r"(a[1]), "r"(a[2]), "r"(a[3]), "r"(b[0]), "r"(b[1]));
}

// per-block dtype probe
__device__ __forceinline__ int probe_is64_block(const void* ei) {
    __shared__ int s_is64;
    if (threadIdx.x == 0) {
        const unsigned* p = (const unsigned*)ei;
        s_is64 = ((p[1] | p[3] | p[5] | p[7]) == 0u) ? 1 : 0;
    }
    __syncthreads();
    return s_is64;
}

__device__ __forceinline__ int clampi(int v) {
    return (v < 0) ? 0 : (v >= NODES ? NODES - 1 : v);
}
__device__ __forceinline__ int load_edge_i(const void* ei, long long idx, int is64) {
    int v;
    if (is64) v = (int)((const long long*)ei)[idx];
    else      v = ((const int*)ei)[idx];
    return clampi(v);
}
// vectorized: 4 consecutive edge ids starting at idx (must be 4-aligned, in-range)
__device__ __forceinline__ void load_edge4(const void* ei, long long idx, int is64, int d[4]) {
    if (is64) {
        const longlong2* p = (const longlong2*)((const long long*)ei + idx);
        longlong2 a = p[0], b = p[1];
        d[0] = clampi((int)a.x); d[1] = clampi((int)a.y);
        d[2] = clampi((int)b.x); d[3] = clampi((int)b.y);
    } else {
        int4 v = *(const int4*)((const int*)ei + idx);
        d[0] = clampi(v.x); d[1] = clampi(v.y);
        d[2] = clampi(v.z); d[3] = clampi(v.w);
    }
}

// ---------------- CSR build (4 edges / thread) ----------------
__global__ void count_edges_k(const void* __restrict__ ei) {
    int is64 = probe_is64_block(ei);
    int e0 = (blockIdx.x * blockDim.x + threadIdx.x) * 4;
    if (e0 >= ETOT) return;
    if (e0 + 4 <= NEDGE) {
        int d[4];
        load_edge4(ei, (long long)NEDGE + e0, is64, d);
        atomicAdd(&g_cnt[d[0]], 1);
        atomicAdd(&g_cnt[d[1]], 1);
        atomicAdd(&g_cnt[d[2]], 1);
        atomicAdd(&g_cnt[d[3]], 1);
    } else {
        int e_hi = e0 + 4 < ETOT ? e0 + 4 : ETOT;
        for (int e = e0; e < e_hi; e++) {
            int dst = (e < NEDGE) ? load_edge_i(ei, (long long)NEDGE + e, is64) : (e - NEDGE);
            atomicAdd(&g_cnt[dst], 1);
        }
    }
}

__global__ void scan_phase1_k() {
    __shared__ int sh[SCAN_BLK];
    int t = threadIdx.x;
    int i = blockIdx.x * SCAN_BLK + t;
    int v = (i < NODES) ? g_cnt[i] : 0;
    sh[t] = v;
    __syncthreads();
    for (int off = 1; off < SCAN_BLK; off <<= 1) {
        int x = 0;
        if (t >= off) x = sh[t - off];
        __syncthreads();
        sh[t] += x;
        __syncthreads();
    }
    if (i < NODES) {
        int loc = sh[t] - v;
        g_rowptr[i] = loc;
        g_fill[i]   = loc;
        g_cnt[i]    = 0;
    }
    if (t == SCAN_BLK - 1) g_tilesum[blockIdx.x] = sh[t];
}

__global__ void scan_phase2_k() {
    __shared__ int sh[64];
    int t = threadIdx.x;
    int v = (t < NTILES) ? g_tilesum[t] : 0;
    sh[t] = v;
    __syncthreads();
    for (int off = 1; off < 64; off <<= 1) {
        int x = 0;
        if (t >= off) x = sh[t - off];
        __syncthreads();
        sh[t] += x;
        __syncthreads();
    }
    if (t < NTILES) g_tileoff[t] = sh[t] - v;
    if (t == 63) g_rowptr[NODES] = sh[63];
}

__global__ void fill_edges_k(const void* __restrict__ ei) {
    int is64 = probe_is64_block(ei);
    int e0 = (blockIdx.x * blockDim.x + threadIdx.x) * 4;
    if (e0 >= ETOT) return;
    if (e0 + 4 <= NEDGE) {
        int s[4], d[4];
        load_edge4(ei, (long long)e0, is64, s);
        load_edge4(ei, (long long)NEDGE + e0, is64, d);
        #pragma unroll
        for (int j = 0; j < 4; j++) {
            int p = atomicAdd(&g_fill[d[j]], 1) + g_tileoff[d[j] >> 10];
            g_col[p] = s[j];
        }
    } else {
        int e_hi = e0 + 4 < ETOT ? e0 + 4 : ETOT;
        for (int e = e0; e < e_hi; e++) {
            int src, dst;
            if (e < NEDGE) {
                src = load_edge_i(ei, e, is64);
                dst = load_edge_i(ei, (long long)NEDGE + e, is64);
            } else {
                src = dst = e - NEDGE;
            }
            int p = atomicAdd(&g_fill[dst], 1) + g_tileoff[dst >> 10];
            g_col[p] = src;
        }
    }
}

// ---------------- TF32 tensor-core GEMM (+ fused attention dots + asmax) -------
#define ASTR 20
#define BSTR 136

template <bool A_EXT, bool BIAS, bool RELU, bool DOTS, bool H16>
__global__ __launch_bounds__(256, 2)
void gemm_tf32_k(const float* __restrict__ Ap, const float* __restrict__ B,
                 const float* __restrict__ bias,
                 const float* __restrict__ a_src, const float* __restrict__ a_dst,
                 int M, int K, int layer) {
    const int BM = 128, BN = 128, BK = 16;
    const float* A = A_EXT ? Ap : (const float*)g_x2;

    __shared__ float As[2][BM][ASTR];
    __shared__ float Bs[2][BK][BSTR];
    __shared__ float sh_s[BM];
    __shared__ float sh_d[BM];

    const int tid  = threadIdx.x;
    const int lane = tid & 31;
    const int wid  = tid >> 5;
    const int wm   = (wid >> 2) * 64;
    const int wn   = (wid & 3) * 32;
    const int gid  = lane >> 2;
    const int tig  = lane & 3;
    const int block_row = blockIdx.x * BM;

    const int a_row  = tid / 4;
    const int a_col4 = tid % 4;
    const int b_row  = tid / 32;
    const int b_col4 = tid % 32;

    if (DOTS && tid < BM) { sh_s[tid] = 0.f; sh_d[tid] = 0.f; }

    float acc[4][4][4];
    #pragma unroll
    for (int mt = 0; mt < 4; mt++)
        #pragma unroll
        for (int nt = 0; nt < 4; nt++)
            #pragma unroll
            for (int r = 0; r < 4; r++) acc[mt][nt][r] = 0.f;

    auto load_tile = [&](int k0, int s) {
        #pragma unroll
        for (int half = 0; half < 2; half++) {
            int r = a_row + half * 64;
            int grow = block_row + r;
            const float* src = A + (size_t)grow * K + k0 + a_col4 * 4;
            uint32_t dst = (uint32_t)__cvta_generic_to_shared(&As[s][r][a_col4 * 4]);
            cp_async16(dst, src, (grow < M) ? 16 : 0);
        }
        #pragma unroll
        for (int half = 0; half < 2; half++) {
            int r = b_row + half * 8;
            const float* src = B + (size_t)(k0 + r) * BN + b_col4 * 4;
            uint32_t dst = (uint32_t)__cvta_generic_to_shared(&Bs[s][r][b_col4 * 4]);
            cp_async16(dst, src, 16);
        }
    };

    load_tile(0, 0);
    cp_commit();

    int buf = 0;
    for (int k0 = 0; k0 < K; k0 += BK) {
        if (k0 + BK < K) load_tile(k0 + BK, buf ^ 1);
        cp_commit();
        cp_wait<1>();
        __syncthreads();

        #pragma unroll
        for (int ks = 0; ks < BK; ks += 8) {
            uint32_t afr[4][4];
            #pragma unroll
            for (int mt = 0; mt < 4; mt++) {
                int r = wm + mt * 16;
                afr[mt][0] = f2tf32(As[buf][r + gid     ][ks + tig    ]);
                afr[mt][1] = f2tf32(As[buf][r + gid + 8 ][ks + tig    ]);
                afr[mt][2] = f2tf32(As[buf][r + gid     ][ks + tig + 4]);
                afr[mt][3] = f2tf32(As[buf][r + gid + 8 ][ks + tig + 4]);
            }
            uint32_t bfr[4][2];
            #pragma unroll
            for (int nt = 0; nt < 4; nt++) {
                int c = wn + nt * 8 + gid;
                bfr[nt][0] = f2tf32(Bs[buf][ks + tig    ][c]);
                bfr[nt][1] = f2tf32(Bs[buf][ks + tig + 4][c]);
            }
            #pragma unroll
            for (int mt = 0; mt < 4; mt++)
                #pragma unroll
                for (int nt = 0; nt < 4; nt++)
                    mma_tf32(acc[mt][nt], afr[mt], bfr[nt]);
        }
        __syncthreads();
        buf ^= 1;
    }
    cp_wait<0>();

    float vs[4][2], vd[4][2];
    if (DOTS) {
        #pragma unroll
        for (int nt = 0; nt < 4; nt++) {
            int col = wn + nt * 8 + 2 * tig;
            vs[nt][0] = a_src[col];     vs[nt][1] = a_src[col + 1];
            vd[nt][0] = a_dst[col];     vd[nt][1] = a_dst[col + 1];
        }
    }

    #pragma unroll
    for (int mt = 0; mt < 4; mt++) {
        #pragma unroll
        for (int half = 0; half < 2; half++) {
            int rloc = wm + mt * 16 + gid + half * 8;
            int grow = block_row + rloc;
            if (grow >= M) continue;
            float ps = 0.f, pd = 0.f;
            #pragma unroll
            for (int nt = 0; nt < 4; nt++) {
                int col = wn + nt * 8 + 2 * tig;
                float v0 = acc[mt][nt][2 * half + 0];
                float v1 = acc[mt][nt][2 * half + 1];
                if (BIAS) { v0 += bias[col]; v1 += bias[col + 1]; }
                if (RELU) { v0 = fmaxf(v0, 0.f); v1 = fmaxf(v1, 0.f); }
                if (DOTS) {
                    ps = fmaf(v0, vs[nt][0], fmaf(v1, vs[nt][1], ps));
                    pd = fmaf(v0, vd[nt][0], fmaf(v1, vd[nt][1], pd));
                }
                if (H16) {
                    __half2 hv = __floats2half2_rn(v0, v1);
                    *reinterpret_cast<__half2*>(g_h16 + (size_t)grow * HID + col) = hv;
                } else {
                    float2* dst = reinterpret_cast<float2*>(g_h + (size_t)grow * HID + col);
                    *dst = make_float2(v0, v1);
                }
            }
            if (DOTS) {
                atomicAdd(&sh_s[rloc], ps);
                atomicAdd(&sh_d[rloc], pd);
            }
        }
    }

    if (DOTS) {
        __syncthreads();
        if (tid < BM) {
            int grow = block_row + tid;
            float sv = -INFINITY;
            if (grow < M) {
                sv = sh_s[tid];
                g_as[grow] = sv;
                g_ad[grow] = sh_d[tid];
            }
            #pragma unroll
            for (int o = 16; o; o >>= 1)
                sv = fmaxf(sv, __shfl_xor_sync(0xffffffffu, sv, o));
            if ((tid & 31) == 0)
                atomicMax(&g_asmax[layer], enc_ord(sv));
        }
    }
}

// ---------------- GAT aggregation: warp/node, single pass w/ global-max bound ----
template <bool RELU>
__global__ void gat_aggregate_k(const float* __restrict__ bias, int layer) {
    int node = blockIdx.x * (blockDim.x >> 5) + (threadIdx.x >> 5);
    if (node >= NODES) return;
    int lane = threadIdx.x & 31;
    int beg = g_rowptr[node] + g_tileoff[node >> 10];
    int end;
    if (node + 1 < NODES) end = g_rowptr[node + 1] + g_tileoff[(node + 1) >> 10];
    else                  end = g_rowptr[NODES];
    float adn = g_ad[node];

    float m = dec_ord(g_asmax[layer]) + adn;
    m = m > 0.f ? m : NEG_SLOPE * m;

    float4 acc = make_float4(0.f, 0.f, 0.f, 0.f);
    float denom = 0.f;
    #pragma unroll 2
    for (int e = beg; e < end; e++) {
        int s = g_col[e];
        float l = g_as[s] + adn;
        l = l > 0.f ? l : NEG_SLOPE * l;
        float w = __expf(l - m);
        denom += w;
        uint2 raw = reinterpret_cast<const uint2*>(g_h16 + (size_t)s * HID)[lane];
        __half2 p0 = *reinterpret_cast<__half2*>(&raw.x);
        __half2 p1 = *reinterpret_cast<__half2*>(&raw.y);
        float2 f0 = __half22float2(p0);
        float2 f1 = __half22float2(p1);
        acc.x = fmaf(w, f0.x, acc.x);
        acc.y = fmaf(w, f0.y, acc.y);
        acc.z = fmaf(w, f1.x, acc.z);
        acc.w = fmaf(w, f1.y, acc.w);
    }
    float inv = 1.f / denom;
    float4 b4 = reinterpret_cast<const float4*>(bias)[lane];
    float4 o4;
    o4.x = acc.x * inv + b4.x;
    o4.y = acc.y * inv + b4.y;
    o4.z = acc.z * inv + b4.z;
    o4.w = acc.w * inv + b4.w;
    if (RELU) {
        o4.x = fmaxf(o4.x, 0.f); o4.y = fmaxf(o4.y, 0.f);
        o4.z = fmaxf(o4.z, 0.f); o4.w = fmaxf(o4.w, 0.f);
    }
    reinterpret_cast<float4*>(g_x2 + (size_t)node * HID)[lane] = o4;
}

// ---------------- final: out = sigmoid(g_h @ Wm2 + bm2), vectorized ----------------
#define MLP_ROWS 64
__global__ __launch_bounds__(256)
void mlp_out_k(const float* __restrict__ W, const float* __restrict__ b,
               float* __restrict__ out) {
    __shared__ float Wst[NCLS][HID + 4];
    __shared__ float bs[NCLS];
    __shared__ __align__(16) float hs[MLP_ROWS][HID];

    int tid = threadIdx.x;
    for (int i = tid; i < HID * NCLS; i += blockDim.x)
        Wst[i % NCLS][i / NCLS] = W[i];
    if (tid < NCLS) bs[tid] = b[tid];

    int row0 = blockIdx.x * MLP_ROWS;
    const float4* src = reinterpret_cast<const float4*>(g_h + (size_t)row0 * HID);
    float4* dst4 = reinterpret_cast<float4*>(&hs[0][0]);
    int n4 = min(MLP_ROWS, NODES - row0) * (HID / 4);
    for (int i = tid; i < n4; i += blockDim.x) dst4[i] = src[i];
    __syncthreads();

    int nout = min(MLP_ROWS, NODES - row0) * NCLS;
    for (int o = tid; o < nout; o += blockDim.x) {
        int rl = o / NCLS, c = o % NCLS;
        const float4* zr = reinterpret_cast<const float4*>(&hs[rl][0]);
        const float4* wc = reinterpret_cast<const float4*>(&Wst[c][0]);
        float acc = bs[c];
        #pragma unroll
        for (int k = 0; k < HID / 4; k++) {
            float4 z = zr[k];
            float4 w = wc[k];
            acc = fmaf(z.x, w.x, acc);
            acc = fmaf(z.y, w.y, acc);
            acc = fmaf(z.z, w.z, acc);
            acc = fmaf(z.w, w.w, acc);
        }
        out[(size_t)(row0 + rl) * NCLS + c] = 1.f / (1.f + __expf(-acc));
    }
}

// ---------------- launch ----------------
extern "C" void kernel_launch(void* const* d_in, const int* in_sizes, int n_in,
                              void* d_out, int out_size) {
    const float* x    = (const float*)d_in[0];
    const void*  ei   = d_in[1];
    const float* W1   = (const float*)d_in[2];
    const float* as1  = (const float*)d_in[3];
    const float* ad1  = (const float*)d_in[4];
    const float* b1   = (const float*)d_in[5];
    const float* W2   = (const float*)d_in[6];
    const float* as2  = (const float*)d_in[7];
    const float* ad2  = (const float*)d_in[8];
    const float* b2   = (const float*)d_in[9];
    const float* Wm1  = (const float*)d_in[10];
    const float* bm1  = (const float*)d_in[11];
    const float* Wm2  = (const float*)d_in[12];
    const float* bm2  = (const float*)d_in[13];
    float*       out  = (float*)d_out;

    const int gemm_grid  = (NODES + 127) / 128;
    const int warps_grid = (NODES + 7) / 8;
    const int edge4_grid = (ETOT / 4 + 256) / 256;   // 4 edges per thread

    // --- fork: CSR build on side stream, GEMM1 on main stream ---
    cudaEventRecord(g_gs.ev_fork, 0);
    cudaStreamWaitEvent(g_gs.side, g_gs.ev_fork, 0);

    count_edges_k<<<edge4_grid, 256, 0, g_gs.side>>>(ei);
    scan_phase1_k<<<NTILES, SCAN_BLK, 0, g_gs.side>>>();
    scan_phase2_k<<<1, 64, 0, g_gs.side>>>();
    fill_edges_k<<<edge4_grid, 256, 0, g_gs.side>>>(ei);
    cudaEventRecord(g_gs.ev_join, g_gs.side);

    // main stream: GAT layer 1 GEMM (+ fused dots/asmax, fp16 h)
    gemm_tf32_k<true, false, false, true, true><<<gemm_grid, 256>>>(x, W1, nullptr, as1, ad1, NODES, FIN, 0);

    cudaStreamWaitEvent(0, g_gs.ev_join, 0);
    gat_aggregate_k<true><<<warps_grid, 256>>>(b1, 0);

    // --- GAT layer 2 ---
    gemm_tf32_k<false, false, false, true, true><<<gemm_grid, 256>>>(nullptr, W2, nullptr, as2, ad2, NODES, HID, 1);
    gat_aggregate_k<false><<<warps_grid, 256>>>(b2, 1);

    // --- MLP head (f32 h) ---
    gemm_tf32_k<false, true, true, false, false><<<gemm_grid, 256>>>(nullptr, Wm1, bm1, nullptr, nullptr, NODES, HID, 0);
    mlp_out_k<<<(NODES + MLP_ROWS - 1) / MLP_ROWS, 256>>>(Wm2, bm2, out);
}

// round 17
// speedup vs baseline: 1.1082x; 1.0312x over previous
#include <cuda_runtime.h>
#include <cuda_fp16.h>
#include <math.h>
#include <stdint.h>

// ---------------- problem constants (fixed by dataset) ----------------
#define NODES 50000
#define NEDGE 600000
#define ETOT  (NEDGE + NODES)   // edges + self loops
#define FIN   256
#define HID   128
#define NCLS  20
#define NEG_SLOPE 0.2f

#define SCAN_BLK 1024
#define NTILES ((NODES + SCAN_BLK - 1) / SCAN_BLK)   // 49

// ---------------- scratch (static device globals) ----------------
__device__ __align__(16) float  g_h  [(size_t)NODES * HID];  // f32 GEMM out (MLP head)
__device__ __align__(16) __half g_h16[(size_t)NODES * HID];  // fp16 GEMM out (GAT layers)
__device__ __align__(16) float  g_x2 [(size_t)NODES * HID];  // aggregation outputs
__device__ __align__(16) float  g_as [NODES];
__device__ __align__(16) float  g_ad [NODES];
__device__ int g_cnt[NODES];
__device__ int g_rowptr[NODES + 1];   // LOCAL exclusive scan per 1024-tile; [NODES]=total
__device__ int g_fill[NODES];
__device__ int g_col[ETOT];
__device__ int g_tilesum[NTILES];
__device__ int g_tileoff[NTILES];
__device__ unsigned g_asmax[2];

// ---------------- streams/events for forked graph capture ----------------
struct GraphStreams {
    cudaStream_t side = nullptr;
    cudaEvent_t ev_fork = nullptr, ev_join = nullptr;
    GraphStreams() {
        cudaStreamCreateWithFlags(&side, cudaStreamNonBlocking);
        cudaEventCreateWithFlags(&ev_fork, cudaEventDisableTiming);
        cudaEventCreateWithFlags(&ev_join, cudaEventDisableTiming);
    }
};
static GraphStreams g_gs;

// ---------------- order-preserving float<->uint encoding ----------------
__device__ __forceinline__ unsigned enc_ord(float f) {
    unsigned u = __float_as_uint(f);
    return (u & 0x80000000u) ? ~u : (u | 0x80000000u);
}
__device__ __forceinline__ float dec_ord(unsigned k) {
    return (k & 0x80000000u) ? __uint_as_float(k & 0x7fffffffu)
                             : __uint_as_float(~k);
}

// ---------------- cp.async helpers ----------------
__device__ __forceinline__ void cp_async16(uint32_t dst, const void* src, int src_bytes) {
    asm volatile("cp.async.cg.shared.global [%0], [%1], 16, %2;"
                 :: "r"(dst), "l"(src), "r"(src_bytes));
}
__device__ __forceinline__ void cp_commit() { asm volatile("cp.async.commit_group;"); }
template <int N>
__device__ __forceinline__ void cp_wait() { asm volatile("cp.async.wait_group %0;" :: "n"(N)); }

__device__ __forceinline__ uint32_t f2tf32(float x) {
    uint32_t r;
    asm("cvt.rna.tf32.f32 %0, %1;" : "=r"(r) : "f"(x));
    return r;
}
__device__ __forceinline__ void mma_tf32(float* d, const uint32_t* a, const uint32_t* b) {
    asm volatile(
        "mma.sync.aligned.m16n8k8.row.col.f32.tf32.tf32.f32 "
        "{%0,%1,%2,%3}, {%4,%5,%6,%7}, {%8,%9}, {%0,%1,%2,%3};"
        : "+f"(d[0]), "+f"(d[1]), "+f"(d[2]), "+f"(d[3])
        : "r"(a[0]), "r"(a[1]), "r"(a[2]), "r"(a[3]), "r"(b[0]), "r"(b[1]));
}

// per-block dtype probe
__device__ __forceinline__ int probe_is64_block(const void* ei) {
    __shared__ int s_is64;
    if (threadIdx.x == 0) {
        const unsigned* p = (const unsigned*)ei;
        s_is64 = ((p[1] | p[3] | p[5] | p[7]) == 0u) ? 1 : 0;
    }
    __syncthreads();
    return s_is64;
}

__device__ __forceinline__ int clampi(int v) {
    return (v < 0) ? 0 : (v >= NODES ? NODES - 1 : v);
}
__device__ __forceinline__ int load_edge_i(const void* ei, long long idx, int is64) {
    int v;
    if (is64) v = (int)((const long long*)ei)[idx];
    else      v = ((const int*)ei)[idx];
    return clampi(v);
}
__device__ __forceinline__ void load_edge4(const void* ei, long long idx, int is64, int d[4]) {
    if (is64) {
        const longlong2* p = (const longlong2*)((const long long*)ei + idx);
        longlong2 a = p[0], b = p[1];
        d[0] = clampi((int)a.x); d[1] = clampi((int)a.y);
        d[2] = clampi((int)b.x); d[3] = clampi((int)b.y);
    } else {
        int4 v = *(const int4*)((const int*)ei + idx);
        d[0] = clampi(v.x); d[1] = clampi(v.y);
        d[2] = clampi(v.z); d[3] = clampi(v.w);
    }
}

// ---------------- CSR build (4 edges / thread) ----------------
__global__ void count_edges_k(const void* __restrict__ ei) {
    int is64 = probe_is64_block(ei);
    int e0 = (blockIdx.x * blockDim.x + threadIdx.x) * 4;
    if (e0 >= ETOT) return;
    if (e0 + 4 <= NEDGE) {
        int d[4];
        load_edge4(ei, (long long)NEDGE + e0, is64, d);
        atomicAdd(&g_cnt[d[0]], 1);
        atomicAdd(&g_cnt[d[1]], 1);
        atomicAdd(&g_cnt[d[2]], 1);
        atomicAdd(&g_cnt[d[3]], 1);
    } else {
        int e_hi = e0 + 4 < ETOT ? e0 + 4 : ETOT;
        for (int e = e0; e < e_hi; e++) {
            int dst = (e < NEDGE) ? load_edge_i(ei, (long long)NEDGE + e, is64) : (e - NEDGE);
            atomicAdd(&g_cnt[dst], 1);
        }
    }
}

__global__ void scan_phase1_k() {
    __shared__ int sh[SCAN_BLK];
    int t = threadIdx.x;
    int i = blockIdx.x * SCAN_BLK + t;
    int v = (i < NODES) ? g_cnt[i] : 0;
    sh[t] = v;
    __syncthreads();
    for (int off = 1; off < SCAN_BLK; off <<= 1) {
        int x = 0;
        if (t >= off) x = sh[t - off];
        __syncthreads();
        sh[t] += x;
        __syncthreads();
    }
    if (i < NODES) {
        int loc = sh[t] - v;
        g_rowptr[i] = loc;
        g_fill[i]   = loc;
        g_cnt[i]    = 0;
    }
    if (t == SCAN_BLK - 1) g_tilesum[blockIdx.x] = sh[t];
}

__global__ void scan_phase2_k() {
    __shared__ int sh[64];
    int t = threadIdx.x;
    int v = (t < NTILES) ? g_tilesum[t] : 0;
    sh[t] = v;
    __syncthreads();
    for (int off = 1; off < 64; off <<= 1) {
        int x = 0;
        if (t >= off) x = sh[t - off];
        __syncthreads();
        sh[t] += x;
        __syncthreads();
    }
    if (t < NTILES) g_tileoff[t] = sh[t] - v;
    if (t == 63) g_rowptr[NODES] = sh[63];
}

__global__ void fill_edges_k(const void* __restrict__ ei) {
    int is64 = probe_is64_block(ei);
    int e0 = (blockIdx.x * blockDim.x + threadIdx.x) * 4;
    if (e0 >= ETOT) return;
    if (e0 + 4 <= NEDGE) {
        int s[4], d[4];
        load_edge4(ei, (long long)e0, is64, s);
        load_edge4(ei, (long long)NEDGE + e0, is64, d);
        #pragma unroll
        for (int j = 0; j < 4; j++) {
            int p = atomicAdd(&g_fill[d[j]], 1) + g_tileoff[d[j] >> 10];
            g_col[p] = s[j];
        }
    } else {
        int e_hi = e0 + 4 < ETOT ? e0 + 4 : ETOT;
        for (int e = e0; e < e_hi; e++) {
            int src, dst;
            if (e < NEDGE) {
                src = load_edge_i(ei, e, is64);
                dst = load_edge_i(ei, (long long)NEDGE + e, is64);
            } else {
                src = dst = e - NEDGE;
            }
            int p = atomicAdd(&g_fill[dst], 1) + g_tileoff[dst >> 10];
            g_col[p] = src;
        }
    }
}

// ---------------- TF32 tensor-core GEMM (+ fused attention dots + asmax) -------
#define ASTR 20
#define BSTR 136

template <bool A_EXT, bool BIAS, bool RELU, bool DOTS, bool H16>
__global__ __launch_bounds__(256, 2)
void gemm_tf32_k(const float* __restrict__ Ap, const float* __restrict__ B,
                 const float* __restrict__ bias,
                 const float* __restrict__ a_src, const float* __restrict__ a_dst,
                 int M, int K, int layer) {
    const int BM = 128, BN = 128, BK = 16;
    const float* A = A_EXT ? Ap : (const float*)g_x2;

    __shared__ float As[2][BM][ASTR];
    __shared__ float Bs[2][BK][BSTR];
    __shared__ float sh_s[BM];
    __shared__ float sh_d[BM];

    const int tid  = threadIdx.x;
    const int lane = tid & 31;
    const int wid  = tid >> 5;
    const int wm   = (wid >> 2) * 64;
    const int wn   = (wid & 3) * 32;
    const int gid  = lane >> 2;
    const int tig  = lane & 3;
    const int block_row = blockIdx.x * BM;

    const int a_row  = tid / 4;
    const int a_col4 = tid % 4;
    const int b_row  = tid / 32;
    const int b_col4 = tid % 32;

    if (DOTS && tid < BM) { sh_s[tid] = 0.f; sh_d[tid] = 0.f; }

    float acc[4][4][4];
    #pragma unroll
    for (int mt = 0; mt < 4; mt++)
        #pragma unroll
        for (int nt = 0; nt < 4; nt++)
            #pragma unroll
            for (int r = 0; r < 4; r++) acc[mt][nt][r] = 0.f;

    auto load_tile = [&](int k0, int s) {
        #pragma unroll
        for (int half = 0; half < 2; half++) {
            int r = a_row + half * 64;
            int grow = block_row + r;
            const float* src = A + (size_t)grow * K + k0 + a_col4 * 4;
            uint32_t dst = (uint32_t)__cvta_generic_to_shared(&As[s][r][a_col4 * 4]);
            cp_async16(dst, src, (grow < M) ? 16 : 0);
        }
        #pragma unroll
        for (int half = 0; half < 2; half++) {
            int r = b_row + half * 8;
            const float* src = B + (size_t)(k0 + r) * BN + b_col4 * 4;
            uint32_t dst = (uint32_t)__cvta_generic_to_shared(&Bs[s][r][b_col4 * 4]);
            cp_async16(dst, src, 16);
        }
    };

    load_tile(0, 0);
    cp_commit();

    int buf = 0;
    for (int k0 = 0; k0 < K; k0 += BK) {
        if (k0 + BK < K) load_tile(k0 + BK, buf ^ 1);
        cp_commit();
        cp_wait<1>();
        __syncthreads();

        #pragma unroll
        for (int ks = 0; ks < BK; ks += 8) {
            uint32_t afr[4][4];
            #pragma unroll
            for (int mt = 0; mt < 4; mt++) {
                int r = wm + mt * 16;
                afr[mt][0] = f2tf32(As[buf][r + gid     ][ks + tig    ]);
                afr[mt][1] = f2tf32(As[buf][r + gid + 8 ][ks + tig    ]);
                afr[mt][2] = f2tf32(As[buf][r + gid     ][ks + tig + 4]);
                afr[mt][3] = f2tf32(As[buf][r + gid + 8 ][ks + tig + 4]);
            }
            uint32_t bfr[4][2];
            #pragma unroll
            for (int nt = 0; nt < 4; nt++) {
                int c = wn + nt * 8 + gid;
                bfr[nt][0] = f2tf32(Bs[buf][ks + tig    ][c]);
                bfr[nt][1] = f2tf32(Bs[buf][ks + tig + 4][c]);
            }
            #pragma unroll
            for (int mt = 0; mt < 4; mt++)
                #pragma unroll
                for (int nt = 0; nt < 4; nt++)
                    mma_tf32(acc[mt][nt], afr[mt], bfr[nt]);
        }
        __syncthreads();
        buf ^= 1;
    }
    cp_wait<0>();

    float vs[4][2], vd[4][2];
    if (DOTS) {
        #pragma unroll
        for (int nt = 0; nt < 4; nt++) {
            int col = wn + nt * 8 + 2 * tig;
            vs[nt][0] = a_src[col];     vs[nt][1] = a_src[col + 1];
            vd[nt][0] = a_dst[col];     vd[nt][1] = a_dst[col + 1];
        }
    }

    #pragma unroll
    for (int mt = 0; mt < 4; mt++) {
        #pragma unroll
        for (int half = 0; half < 2; half++) {
            int rloc = wm + mt * 16 + gid + half * 8;
            int grow = block_row + rloc;
            if (grow >= M) continue;
            float ps = 0.f, pd = 0.f;
            #pragma unroll
            for (int nt = 0; nt < 4; nt++) {
                int col = wn + nt * 8 + 2 * tig;
                float v0 = acc[mt][nt][2 * half + 0];
                float v1 = acc[mt][nt][2 * half + 1];
                if (BIAS) { v0 += bias[col]; v1 += bias[col + 1]; }
                if (RELU) { v0 = fmaxf(v0, 0.f); v1 = fmaxf(v1, 0.f); }
                if (DOTS) {
                    ps = fmaf(v0, vs[nt][0], fmaf(v1, vs[nt][1], ps));
                    pd = fmaf(v0, vd[nt][0], fmaf(v1, vd[nt][1], pd));
                }
                if (H16) {
                    __half2 hv = __floats2half2_rn(v0, v1);
                    *reinterpret_cast<__half2*>(g_h16 + (size_t)grow * HID + col) = hv;
                } else {
                    float2* dst = reinterpret_cast<float2*>(g_h + (size_t)grow * HID + col);
                    *dst = make_float2(v0, v1);
                }
            }
            if (DOTS) {
                atomicAdd(&sh_s[rloc], ps);
                atomicAdd(&sh_d[rloc], pd);
            }
        }
    }

    if (DOTS) {
        __syncthreads();
        if (tid < BM) {
            int grow = block_row + tid;
            float sv = -INFINITY;
            if (grow < M) {
                sv = sh_s[tid];
                g_as[grow] = sv;
                g_ad[grow] = sh_d[tid];
            }
            #pragma unroll
            for (int o = 16; o; o >>= 1)
                sv = fmaxf(sv, __shfl_xor_sync(0xffffffffu, sv, o));
            if ((tid & 31) == 0)
                atomicMax(&g_asmax[layer], enc_ord(sv));
        }
    }
}

// ---------------- GAT aggregation: 2 nodes per warp (16 lanes each) ------------
// Each half-warp serves one node; lane owns 8 fp16 cols (uint4 = 16B).
// Scalar chain (col/as loads, leaky, exp, denom) shared as single warp insts.
template <bool RELU>
__global__ void gat_aggregate_k(const float* __restrict__ bias, int layer) {
    int warp = blockIdx.x * (blockDim.x >> 5) + (threadIdx.x >> 5);
    int halfid = (threadIdx.x >> 4) & 1;
    int node = warp * 2 + halfid;
    int lane16 = threadIdx.x & 15;
    bool valid = (node < NODES);
    int nclamp = valid ? node : NODES - 1;

    int beg = g_rowptr[nclamp] + g_tileoff[nclamp >> 10];
    int end;
    if (nclamp + 1 < NODES) end = g_rowptr[nclamp + 1] + g_tileoff[(nclamp + 1) >> 10];
    else                    end = g_rowptr[NODES];
    int len = end - beg;                      // >= 1 (self loop)
    float adn = g_ad[nclamp];

    // warp loop bound = max(lenA, lenB)
    int maxlen = max(len, __shfl_xor_sync(0xffffffffu, len, 16));

    // stabilizer: leaky(AS_MAX + adn) >= node max (leaky monotone, softmax shift-inv)
    float m = dec_ord(g_asmax[layer]) + adn;
    m = m > 0.f ? m : NEG_SLOPE * m;

    float acc[8];
    #pragma unroll
    for (int j = 0; j < 8; j++) acc[j] = 0.f;
    float denom = 0.f;

    for (int i = 0; i < maxlen; i++) {
        int ii = i < len - 1 ? i : len - 1;   // clamp to last valid edge
        int e = beg + ii;
        float live = (i < len) ? 1.f : 0.f;
        int s = g_col[e];                     // broadcast within half
        float l = g_as[s] + adn;
        l = l > 0.f ? l : NEG_SLOPE * l;
        float w = __expf(l - m) * live;
        denom += w;
        uint4 raw = reinterpret_cast<const uint4*>(g_h16 + (size_t)s * HID)[lane16];
        __half2 p0 = *reinterpret_cast<__half2*>(&raw.x);
        __half2 p1 = *reinterpret_cast<__half2*>(&raw.y);
        __half2 p2 = *reinterpret_cast<__half2*>(&raw.z);
        __half2 p3 = *reinterpret_cast<__half2*>(&raw.w);
        float2 f0 = __half22float2(p0);
        float2 f1 = __half22float2(p1);
        float2 f2 = __half22float2(p2);
        float2 f3 = __half22float2(p3);
        acc[0] = fmaf(w, f0.x, acc[0]);
        acc[1] = fmaf(w, f0.y, acc[1]);
        acc[2] = fmaf(w, f1.x, acc[2]);
        acc[3] = fmaf(w, f1.y, acc[3]);
        acc[4] = fmaf(w, f2.x, acc[4]);
        acc[5] = fmaf(w, f2.y, acc[5]);
        acc[6] = fmaf(w, f3.x, acc[6]);
        acc[7] = fmaf(w, f3.y, acc[7]);
    }

    if (!valid) return;
    float inv = 1.f / denom;
    const float* bp = bias + lane16 * 8;
    float4 b0 = reinterpret_cast<const float4*>(bp)[0];
    float4 b1 = reinterpret_cast<const float4*>(bp)[1];
    float o[8];
    o[0] = acc[0] * inv + b0.x;  o[1] = acc[1] * inv + b0.y;
    o[2] = acc[2] * inv + b0.z;  o[3] = acc[3] * inv + b0.w;
    o[4] = acc[4] * inv + b1.x;  o[5] = acc[5] * inv + b1.y;
    o[6] = acc[6] * inv + b1.z;  o[7] = acc[7] * inv + b1.w;
    if (RELU) {
        #pragma unroll
        for (int j = 0; j < 8; j++) o[j] = fmaxf(o[j], 0.f);
    }
    float4* outp = reinterpret_cast<float4*>(g_x2 + (size_t)node * HID + lane16 * 8);
    outp[0] = make_float4(o[0], o[1], o[2], o[3]);
    outp[1] = make_float4(o[4], o[5], o[6], o[7]);
}

// ---------------- final: out = sigmoid(g_h @ Wm2 + bm2), vectorized ----------------
#define MLP_ROWS 64
__global__ __launch_bounds__(256)
void mlp_out_k(const float* __restrict__ W, const float* __restrict__ b,
               float* __restrict__ out) {
    __shared__ float Wst[NCLS][HID + 4];
    __shared__ float bs[NCLS];
    __shared__ __align__(16) float hs[MLP_ROWS][HID];

    int tid = threadIdx.x;
    for (int i = tid; i < HID * NCLS; i += blockDim.x)
        Wst[i % NCLS][i / NCLS] = W[i];
    if (tid < NCLS) bs[tid] = b[tid];

    int row0 = blockIdx.x * MLP_ROWS;
    const float4* src = reinterpret_cast<const float4*>(g_h + (size_t)row0 * HID);
    float4* dst4 = reinterpret_cast<float4*>(&hs[0][0]);
    int n4 = min(MLP_ROWS, NODES - row0) * (HID / 4);
    for (int i = tid; i < n4; i += blockDim.x) dst4[i] = src[i];
    __syncthreads();

    int nout = min(MLP_ROWS, NODES - row0) * NCLS;
    for (int o = tid; o < nout; o += blockDim.x) {
        int rl = o / NCLS, c = o % NCLS;
        const float4* zr = reinterpret_cast<const float4*>(&hs[rl][0]);
        const float4* wc = reinterpret_cast<const float4*>(&Wst[c][0]);
        float acc = bs[c];
        #pragma unroll
        for (int k = 0; k < HID / 4; k++) {
            float4 z = zr[k];
            float4 w = wc[k];
            acc = fmaf(z.x, w.x, acc);
            acc = fmaf(z.y, w.y, acc);
            acc = fmaf(z.z, w.z, acc);
            acc = fmaf(z.w, w.w, acc);
        }
        out[(size_t)(row0 + rl) * NCLS + c] = 1.f / (1.f + __expf(-acc));
    }
}

// ---------------- launch ----------------
extern "C" void kernel_launch(void* const* d_in, const int* in_sizes, int n_in,
                              void* d_out, int out_size) {
    const float* x    = (const float*)d_in[0];
    const void*  ei   = d_in[1];
    const float* W1   = (const float*)d_in[2];
    const float* as1  = (const float*)d_in[3];
    const float* ad1  = (const float*)d_in[4];
    const float* b1   = (const float*)d_in[5];
    const float* W2   = (const float*)d_in[6];
    const float* as2  = (const float*)d_in[7];
    const float* ad2  = (const float*)d_in[8];
    const float* b2   = (const float*)d_in[9];
    const float* Wm1  = (const float*)d_in[10];
    const float* bm1  = (const float*)d_in[11];
    const float* Wm2  = (const float*)d_in[12];
    const float* bm2  = (const float*)d_in[13];
    float*       out  = (float*)d_out;

    const int gemm_grid  = (NODES + 127) / 128;
    const int pairs_grid = ((NODES + 1) / 2 + 7) / 8;   // 2 nodes/warp, 8 warps/block
    const int edge4_grid = (ETOT / 4 + 256) / 256;

    // --- fork: CSR build on side stream, GEMM1 on main stream ---
    cudaEventRecord(g_gs.ev_fork, 0);
    cudaStreamWaitEvent(g_gs.side, g_gs.ev_fork, 0);

    count_edges_k<<<edge4_grid, 256, 0, g_gs.side>>>(ei);
    scan_phase1_k<<<NTILES, SCAN_BLK, 0, g_gs.side>>>();
    scan_phase2_k<<<1, 64, 0, g_gs.side>>>();
    fill_edges_k<<<edge4_grid, 256, 0, g_gs.side>>>(ei);
    cudaEventRecord(g_gs.ev_join, g_gs.side);

    // main stream: GAT layer 1 GEMM (+ fused dots/asmax, fp16 h)
    gemm_tf32_k<true, false, false, true, true><<<gemm_grid, 256>>>(x, W1, nullptr, as1, ad1, NODES, FIN, 0);

    cudaStreamWaitEvent(0, g_gs.ev_join, 0);
    gat_aggregate_k<true><<<pairs_grid, 256>>>(b1, 0);

    // --- GAT layer 2 ---
    gemm_tf32_k<false, false, false, true, true><<<gemm_grid, 256>>>(nullptr, W2, nullptr, as2, ad2, NODES, HID, 1);
    gat_aggregate_k<false><<<pairs_grid, 256>>>(b2, 1);

    // --- MLP head (f32 h) ---
    gemm_tf32_k<false, true, true, false, false><<<gemm_grid, 256>>>(nullptr, Wm1, bm1, nullptr, nullptr, NODES, HID, 0);
    mlp_out_k<<<(NODES + MLP_ROWS - 1) / MLP_ROWS, 256>>>(Wm2, bm2, out);
}